// round 1
// baseline (speedup 1.0000x reference)
#include <cuda_runtime.h>

#define B_   256
#define M_   8
#define L_   64
#define E_   128
#define H_   8
#define HD_  16
#define QKV_ 384
#define BCHUNK 32

// Scratch (no allocation allowed -> __device__ globals)
__device__ float g_agg0[B_ * M_ * E_];     // mean-fused walk aggregate [B][M][E]
__device__ float g_agg1[B_ * M_ * E_];     // after per-metapath linear [B][M][E]
__device__ float g_WqkvT[E_ * QKV_];       // Wqkv transposed: [e][j]
__device__ float g_WoT[E_ * E_];           // Wo transposed:   [e][j]

// ---------------------------------------------------------------------------
// Kernel T: transpose Wqkv [384][128] -> [128][384], Wo [128][128] -> [128][128]
// ---------------------------------------------------------------------------
__global__ void k_transpose(const float* __restrict__ Wqkv,
                            const float* __restrict__ Wo) {
    int tid = blockIdx.x * blockDim.x + threadIdx.x;
    if (tid < E_ * QKV_) {
        int j = tid / E_;   // 0..383 (row of Wqkv)
        int e = tid % E_;
        g_WqkvT[e * QKV_ + j] = Wqkv[j * E_ + e];
    }
    if (tid < E_ * E_) {
        int j = tid / E_;
        int e = tid % E_;
        g_WoT[e * E_ + j] = Wo[j * E_ + e];
    }
}

// ---------------------------------------------------------------------------
// Kernel A: gather + elementwise fuse + mean over walk steps
// block = (b*M + m), thread = e.  Random 512B-row gathers from node_table.
// ---------------------------------------------------------------------------
__global__ void k_gather(const int*   __restrict__ walks,
                         const float* __restrict__ node_table,
                         const float* __restrict__ fc1_b,
                         const float* __restrict__ edge_table) {
    __shared__ int s_idx[L_ * 3];
    const int bid = blockIdx.x;           // b*M + m
    const int tid = threadIdx.x;          // e in [0,128)
    const int base = bid * (L_ * 3);
    for (int i = tid; i < L_ * 3; i += E_) s_idx[i] = walks[base + i];
    __syncthreads();

    const float fb = fc1_b[tid];
    float acc = 0.f;
#pragma unroll 4
    for (int l = 0; l < L_; l++) {
        int n1 = s_idx[3 * l + 0];
        int n2 = s_idx[3 * l + 1];
        int et = s_idx[3 * l + 2];
        float a = node_table[n1 * E_ + tid] + fb;
        float b = node_table[n2 * E_ + tid] + fb;
        float c = edge_table[et * E_ + tid];
        acc += a * b * c;
    }
    g_agg0[bid * E_ + tid] = acc * (1.f / (float)L_);
}

// ---------------------------------------------------------------------------
// Kernel B: per-metapath linear  agg1[b,m,:] = agg0[b,m,:] @ W_mp[mt] + b_mp[mt]
// block = (m, chunk of 32 b), thread = output column o.
// ---------------------------------------------------------------------------
__global__ void k_mplinear(const int*   __restrict__ mp_type_idx,
                           const float* __restrict__ W_mp,
                           const float* __restrict__ b_mp) {
    __shared__ float s_agg[BCHUNK][E_];   // 16 KB
    const int m   = blockIdx.x;           // 0..7
    const int bc  = blockIdx.y;           // 0..7
    const int tid = threadIdx.x;          // o in [0,128)
    const int b0  = bc * BCHUNK;

    for (int i = tid; i < BCHUNK * E_; i += E_) {
        int j = i >> 7;                   // i / 128
        int e = i & 127;
        s_agg[j][e] = g_agg0[(b0 + j) * (M_ * E_) + m * E_ + e];
    }
    __syncthreads();

    const int mt = mp_type_idx[m];
    const float* W = W_mp + mt * (E_ * E_);

    float acc[BCHUNK];
#pragma unroll
    for (int j = 0; j < BCHUNK; j++) acc[j] = 0.f;

    for (int e = 0; e < E_; e++) {
        float w = W[e * E_ + tid];        // coalesced across lanes
#pragma unroll
        for (int j = 0; j < BCHUNK; j++) acc[j] += s_agg[j][e] * w;  // smem broadcast
    }
    const float bv = b_mp[mt * E_ + tid];
#pragma unroll
    for (int j = 0; j < BCHUNK; j++)
        g_agg1[(b0 + j) * (M_ * E_) + m * E_ + tid] = acc[j] + bv;
}

// ---------------------------------------------------------------------------
// Kernel C: fused MHA over metapaths (seq len M=8, heads H=8, hd=16)
// block handles 2 batch rows; 256 threads; everything in 32 KB smem.
// ---------------------------------------------------------------------------
__global__ void k_attn(const float* __restrict__ bqkv,
                       const float* __restrict__ bo,
                       float* __restrict__ out) {
    __shared__ float s_x[2][M_][E_];      // 8 KB: input x, later reused for attn output o
    __shared__ float s_qkv[2][M_][QKV_];  // 24 KB

    const int tid = threadIdx.x;
    const int bl  = tid >> 7;             // 0..1 (local batch row)
    const int j   = tid & 127;            // column
    const int b0  = blockIdx.x * 2;

    // ---- load x = agg1 for these 2 batch rows (contiguous) ----
    float* xf = &s_x[0][0][0];
    for (int i = tid; i < 2 * M_ * E_; i += 256)
        xf[i] = g_agg1[b0 * (M_ * E_) + i];
    __syncthreads();

    // ---- QKV projection: qkv[m][j'] = x[m,:] @ WqkvT[:,j'] + bqkv ----
    float aq[M_], ak[M_], av[M_];
    const float bq = bqkv[j], bk = bqkv[E_ + j], bv = bqkv[2 * E_ + j];
#pragma unroll
    for (int m = 0; m < M_; m++) { aq[m] = bq; ak[m] = bk; av[m] = bv; }

    for (int e = 0; e < E_; e++) {
        float w0 = g_WqkvT[e * QKV_ + j];
        float w1 = g_WqkvT[e * QKV_ + E_ + j];
        float w2 = g_WqkvT[e * QKV_ + 2 * E_ + j];
#pragma unroll
        for (int m = 0; m < M_; m++) {
            float xv = s_x[bl][m][e];
            aq[m] += xv * w0;
            ak[m] += xv * w1;
            av[m] += xv * w2;
        }
    }
#pragma unroll
    for (int m = 0; m < M_; m++) {
        s_qkv[bl][m][j]          = aq[m];
        s_qkv[bl][m][E_ + j]     = ak[m];
        s_qkv[bl][m][2 * E_ + j] = av[m];
    }
    __syncthreads();

    // ---- attention: one thread per (bl, h, m); 2*8*8 = 128 items ----
    if (tid < 128) {
        const int bl2 = tid >> 6;
        const int h   = (tid >> 3) & 7;
        const int mm  = tid & 7;
        const float* q = &s_qkv[bl2][mm][h * HD_];

        float s[M_];
        float mx = -1e30f;
#pragma unroll
        for (int n = 0; n < M_; n++) {
            const float* kv = &s_qkv[bl2][n][E_ + h * HD_];
            float d = 0.f;
#pragma unroll
            for (int t = 0; t < HD_; t++) d += q[t] * kv[t];
            s[n] = d * 0.25f;             // 1/sqrt(16)
            mx = fmaxf(mx, s[n]);
        }
        float sum = 0.f;
#pragma unroll
        for (int n = 0; n < M_; n++) { s[n] = __expf(s[n] - mx); sum += s[n]; }
        const float inv = 1.f / sum;

        float o[HD_];
#pragma unroll
        for (int t = 0; t < HD_; t++) o[t] = 0.f;
#pragma unroll
        for (int n = 0; n < M_; n++) {
            float p = s[n] * inv;
            const float* vv = &s_qkv[bl2][n][2 * E_ + h * HD_];
#pragma unroll
            for (int t = 0; t < HD_; t++) o[t] += p * vv[t];
        }
        // write attn head output into s_x (x no longer needed)
#pragma unroll
        for (int t = 0; t < HD_; t++) s_x[bl2][mm][h * HD_ + t] = o[t];
    }
    __syncthreads();

    // ---- output projection: out[m, b, j] = o[m,:] @ WoT[:,j] + bo[j] ----
    float acc2[M_];
    const float boj = bo[j];
#pragma unroll
    for (int m = 0; m < M_; m++) acc2[m] = boj;
    for (int e = 0; e < E_; e++) {
        float w = g_WoT[e * E_ + j];
#pragma unroll
        for (int m = 0; m < M_; m++) acc2[m] += s_x[bl][m][e] * w;
    }
    const int b = b0 + bl;
#pragma unroll
    for (int m = 0; m < M_; m++)
        out[m * (B_ * E_) + b * E_ + j] = acc2[m];
}

// ---------------------------------------------------------------------------
extern "C" void kernel_launch(void* const* d_in, const int* in_sizes, int n_in,
                              void* d_out, int out_size) {
    (void)in_sizes; (void)n_in; (void)out_size;
    // inputs in setup_inputs() order
    const int*   node_idx    = (const int*)d_in[0];  (void)node_idx;  // unused by reference
    const int*   mp_type_idx = (const int*)d_in[1];
    const int*   walks       = (const int*)d_in[2];
    const float* node_table  = (const float*)d_in[3];
    const float* fc1_b       = (const float*)d_in[4];
    const float* edge_table  = (const float*)d_in[5];
    const float* W_mp        = (const float*)d_in[6];
    const float* b_mp        = (const float*)d_in[7];
    const float* Wqkv        = (const float*)d_in[8];
    const float* bqkv        = (const float*)d_in[9];
    const float* Wo          = (const float*)d_in[10];
    const float* bo          = (const float*)d_in[11];
    float* out = (float*)d_out;

    k_transpose<<<(E_ * QKV_ + 255) / 256, 256>>>(Wqkv, Wo);
    k_gather<<<B_ * M_, E_>>>(walks, node_table, fc1_b, edge_table);
    dim3 gB(M_, B_ / BCHUNK);
    k_mplinear<<<gB, E_>>>(mp_type_idx, W_mp, b_mp);
    k_attn<<<B_ / 2, 256>>>(bqkv, bo, out);
}

// round 2
// speedup vs baseline: 1.7097x; 1.7097x over previous
#include <cuda_runtime.h>

#define B_   256
#define M_   8
#define L_   64
#define E_   128
#define H_   8
#define HD_  16
#define QKV_ 384
#define BCHUNK 8

// Scratch (no allocation allowed -> __device__ globals)
__device__ float g_agg0[B_ * M_ * E_];     // mean-fused walk aggregate [B][M][E]
__device__ float g_agg1[B_ * M_ * E_];     // after per-metapath linear [B][M][E]
__device__ float g_WqkvT[E_ * QKV_];       // Wqkv transposed: [e][j]
__device__ float g_WoT[E_ * E_];           // Wo transposed:   [e][j]

// ---------------------------------------------------------------------------
// Kernel T: transpose Wqkv [384][128] -> [128][384], Wo [128][128] -> [128][128]
// ---------------------------------------------------------------------------
__global__ void k_transpose(const float* __restrict__ Wqkv,
                            const float* __restrict__ Wo) {
    int tid = blockIdx.x * blockDim.x + threadIdx.x;
    if (tid < E_ * QKV_) {
        int j = tid / E_;   // 0..383 (row of Wqkv)
        int e = tid % E_;
        g_WqkvT[e * QKV_ + j] = Wqkv[j * E_ + e];
    }
    if (tid < E_ * E_) {
        int j = tid / E_;
        int e = tid % E_;
        g_WoT[e * E_ + j] = Wo[j * E_ + e];
    }
}

// ---------------------------------------------------------------------------
// Kernel A: gather + elementwise fuse + mean over walk steps
// block = (b*M + m), thread = e.  Random 512B-row gathers from node_table.
// ---------------------------------------------------------------------------
__global__ void k_gather(const int*   __restrict__ walks,
                         const float* __restrict__ node_table,
                         const float* __restrict__ fc1_b,
                         const float* __restrict__ edge_table) {
    __shared__ int s_idx[L_ * 3];
    const int bid = blockIdx.x;           // b*M + m
    const int tid = threadIdx.x;          // e in [0,128)
    const int base = bid * (L_ * 3);
    for (int i = tid; i < L_ * 3; i += E_) s_idx[i] = walks[base + i];
    __syncthreads();

    const float fb = fc1_b[tid];
    float acc = 0.f;
#pragma unroll 8
    for (int l = 0; l < L_; l++) {
        int n1 = s_idx[3 * l + 0];
        int n2 = s_idx[3 * l + 1];
        int et = s_idx[3 * l + 2];
        float a = node_table[n1 * E_ + tid] + fb;
        float b = node_table[n2 * E_ + tid] + fb;
        float c = edge_table[et * E_ + tid];
        acc += a * b * c;
    }
    g_agg0[bid * E_ + tid] = acc * (1.f / (float)L_);
}

// ---------------------------------------------------------------------------
// Kernel B: per-metapath linear  agg1[b,m,:] = agg0[b,m,:] @ W_mp[mt] + b_mp[mt]
// block = (m, chunk of 8 b), thread = output column o.  256 blocks.
// ---------------------------------------------------------------------------
__global__ void k_mplinear(const int*   __restrict__ mp_type_idx,
                           const float* __restrict__ W_mp,
                           const float* __restrict__ b_mp) {
    __shared__ float s_agg[BCHUNK][E_];   // 4 KB
    const int m   = blockIdx.x;           // 0..7
    const int bc  = blockIdx.y;           // 0..31
    const int tid = threadIdx.x;          // o in [0,128)
    const int b0  = bc * BCHUNK;

    for (int i = tid; i < BCHUNK * E_; i += E_) {
        int j = i >> 7;                   // i / 128
        int e = i & 127;
        s_agg[j][e] = g_agg0[(b0 + j) * (M_ * E_) + m * E_ + e];
    }
    __syncthreads();

    const int mt = mp_type_idx[m];
    const float* W = W_mp + mt * (E_ * E_);

    float acc[BCHUNK];
#pragma unroll
    for (int j = 0; j < BCHUNK; j++) acc[j] = 0.f;

#pragma unroll 4
    for (int e = 0; e < E_; e++) {
        float w = W[e * E_ + tid];        // coalesced across lanes
#pragma unroll
        for (int j = 0; j < BCHUNK; j++) acc[j] += s_agg[j][e] * w;  // smem broadcast
    }
    const float bv = b_mp[mt * E_ + tid];
#pragma unroll
    for (int j = 0; j < BCHUNK; j++)
        g_agg1[(b0 + j) * (M_ * E_) + m * E_ + tid] = acc[j] + bv;
}

// ---------------------------------------------------------------------------
// Kernel C: fused MHA over metapaths (seq len M=8, heads H=8, hd=16)
// One batch row per block, 384 threads (one per QKV output column). 256 blocks.
// ---------------------------------------------------------------------------
__global__ void __launch_bounds__(QKV_) k_attn(const float* __restrict__ bqkv,
                                               const float* __restrict__ bo,
                                               float* __restrict__ out) {
    __shared__ float s_x[M_][E_];         // 4 KB  (input x)
    __shared__ float s_qkv[M_][QKV_];     // 12 KB
    __shared__ float s_o[M_][E_];         // 4 KB  (attn head output)

    const int tid = threadIdx.x;          // 0..383
    const int b   = blockIdx.x;

    // ---- load x = agg1 for this batch row (contiguous 4 KB) ----
    {
        float* xf = &s_x[0][0];
        for (int i = tid; i < M_ * E_; i += QKV_)
            xf[i] = g_agg1[b * (M_ * E_) + i];
    }
    __syncthreads();

    // ---- QKV projection: qkv[m][tid] = x[m,:] @ WqkvT[:,tid] + bqkv[tid] ----
    {
        float acc[M_];
        const float bj = bqkv[tid];
#pragma unroll
        for (int m = 0; m < M_; m++) acc[m] = bj;

#pragma unroll 4
        for (int e = 0; e < E_; e++) {
            float w = g_WqkvT[e * QKV_ + tid];
#pragma unroll
            for (int m = 0; m < M_; m++) acc[m] += s_x[m][e] * w;   // smem broadcast
        }
#pragma unroll
        for (int m = 0; m < M_; m++) s_qkv[m][tid] = acc[m];
    }
    __syncthreads();

    // ---- attention: one thread per (h, m); 8*8 = 64 items ----
    if (tid < H_ * M_) {
        const int h  = tid >> 3;
        const int mm = tid & 7;
        const float* q = &s_qkv[mm][h * HD_];

        float s[M_];
        float mx = -1e30f;
#pragma unroll
        for (int n = 0; n < M_; n++) {
            const float* kv = &s_qkv[n][E_ + h * HD_];
            float d = 0.f;
#pragma unroll
            for (int t = 0; t < HD_; t++) d += q[t] * kv[t];
            s[n] = d * 0.25f;             // 1/sqrt(16)
            mx = fmaxf(mx, s[n]);
        }
        float sum = 0.f;
#pragma unroll
        for (int n = 0; n < M_; n++) { s[n] = __expf(s[n] - mx); sum += s[n]; }
        const float inv = 1.f / sum;

        float o[HD_];
#pragma unroll
        for (int t = 0; t < HD_; t++) o[t] = 0.f;
#pragma unroll
        for (int n = 0; n < M_; n++) {
            float p = s[n] * inv;
            const float* vv = &s_qkv[n][2 * E_ + h * HD_];
#pragma unroll
            for (int t = 0; t < HD_; t++) o[t] += p * vv[t];
        }
#pragma unroll
        for (int t = 0; t < HD_; t++) s_o[mm][h * HD_ + t] = o[t];
    }
    __syncthreads();

    // ---- output projection: 1024 outputs striped over 384 threads ----
    for (int idx = tid; idx < M_ * E_; idx += QKV_) {
        const int m = idx >> 7;
        const int j = idx & 127;
        float a = bo[j];
#pragma unroll 4
        for (int e = 0; e < E_; e++)
            a += s_o[m][e] * g_WoT[e * E_ + j];
        out[m * (B_ * E_) + b * E_ + j] = a;
    }
}

// ---------------------------------------------------------------------------
extern "C" void kernel_launch(void* const* d_in, const int* in_sizes, int n_in,
                              void* d_out, int out_size) {
    (void)in_sizes; (void)n_in; (void)out_size;
    // inputs in setup_inputs() order
    const int*   node_idx    = (const int*)d_in[0];  (void)node_idx;  // unused by reference
    const int*   mp_type_idx = (const int*)d_in[1];
    const int*   walks       = (const int*)d_in[2];
    const float* node_table  = (const float*)d_in[3];
    const float* fc1_b       = (const float*)d_in[4];
    const float* edge_table  = (const float*)d_in[5];
    const float* W_mp        = (const float*)d_in[6];
    const float* b_mp        = (const float*)d_in[7];
    const float* Wqkv        = (const float*)d_in[8];
    const float* bqkv        = (const float*)d_in[9];
    const float* Wo          = (const float*)d_in[10];
    const float* bo          = (const float*)d_in[11];
    float* out = (float*)d_out;

    k_transpose<<<(E_ * QKV_ + 255) / 256, 256>>>(Wqkv, Wo);
    k_gather<<<B_ * M_, E_>>>(walks, node_table, fc1_b, edge_table);
    dim3 gB(M_, B_ / BCHUNK);
    k_mplinear<<<gB, E_>>>(mp_type_idx, W_mp, b_mp);
    k_attn<<<B_, QKV_>>>(bqkv, bo, out);
}